// round 16
// baseline (speedup 1.0000x reference)
#include <cuda_runtime.h>
#include <cuda_bf16.h>

#define EPSBN 1e-5f
#define ALPHA 0.2f

typedef unsigned long long ull;
typedef unsigned int u32;
typedef unsigned short u16;

static constexpr int B = 16, N = 4096, P = 1024;
static constexpr int NTILES = (B * P) / 4;
static constexpr int OUT2_OFF = B * 3 * P;
static constexpr int THREADS = 512;

// [b][n][0..63]=feats, [64..66]=xyz, [67]=0
__device__ __align__(16) float g_xpt[(size_t)B * N * 68];
__device__ __align__(16) float g_aT[128 * 132];
__device__ __align__(16) u16 g_aTh[128 * 136];
__device__ __align__(16) u16 g_aTl[128 * 136];
__device__ __align__(16) float g_axyz[512];
__device__ __align__(16) float g_Fp[(size_t)B * P * 128];

// ---------------- helpers ----------------
__device__ __forceinline__ void ffma2(ull& d, ull a, ull b) {
    asm("fma.rn.f32x2 %0, %1, %2, %0;" : "+l"(d) : "l"(a), "l"(b));
}
__device__ __forceinline__ float hsum2(ull v) {
    float lo, hi; asm("mov.b64 {%0, %1}, %2;" : "=f"(lo), "=f"(hi) : "l"(v));
    return lo + hi;
}
__device__ __forceinline__ float bf2f(u16 v) { return __uint_as_float(((u32)v) << 16); }
__device__ __forceinline__ void bfsplit(float x, u16& h, u16& l) {
    __nv_bfloat16 bh = __float2bfloat16(x);
    h = __nv_bfloat16_raw(bh).x;
    l = __nv_bfloat16_raw(__float2bfloat16(x - __bfloat162float(bh))).x;
}
__device__ __forceinline__ u32 smem_u32(const void* p) {
    u32 a; asm("{ .reg .u64 t; cvta.to.shared.u64 t, %1; cvt.u32.u64 %0, t; }"
               : "=r"(a) : "l"(p));
    return a;
}
__device__ __forceinline__ void ldm_x4(u32* f, u32 addr) {
    asm volatile("ldmatrix.sync.aligned.m8n8.x4.shared.b16 {%0,%1,%2,%3}, [%4];"
        : "=r"(f[0]), "=r"(f[1]), "=r"(f[2]), "=r"(f[3]) : "r"(addr));
}
__device__ __forceinline__ void ldm_x2(u32* f, u32 addr) {
    asm volatile("ldmatrix.sync.aligned.m8n8.x2.shared.b16 {%0,%1}, [%2];"
        : "=r"(f[0]), "=r"(f[1]) : "r"(addr));
}
__device__ __forceinline__ void mma_bf16(float* c, const u32* a, const u32* b) {
    asm volatile("mma.sync.aligned.m16n8k16.row.col.f32.bf16.bf16.f32 "
        "{%0,%1,%2,%3},{%4,%5,%6,%7},{%8,%9},{%0,%1,%2,%3};"
        : "+f"(c[0]), "+f"(c[1]), "+f"(c[2]), "+f"(c[3])
        : "r"(a[0]), "r"(a[1]), "r"(a[2]), "r"(a[3]), "r"(b[0]), "r"(b[1]));
}

// ---------------- transpose (feats first) ----------------
__global__ void __launch_bounds__(256) transpose_kernel(
    const float* __restrict__ xyz, const float* __restrict__ pts)
{
    __shared__ float sm[67 * 65];
    int b = blockIdx.x >> 6, n0 = (blockIdx.x & 63) << 6, t = threadIdx.x;
    for (int idx = t; idx < 67 * 64; idx += 256) {
        int c = idx >> 6, i = idx & 63;
        sm[c * 65 + i] = (c < 64) ? pts[(b * 64 + c) * N + n0 + i]
                                  : xyz[(b * 3 + (c - 64)) * N + n0 + i];
    }
    __syncthreads();
    for (int idx = t; idx < 64 * 17; idx += 256) {
        int row = idx / 17, cb = (idx % 17) << 2;
        float4 v;
        v.x = sm[(cb + 0) * 65 + row];
        v.y = sm[(cb + 1) * 65 + row];
        v.z = sm[(cb + 2) * 65 + row];
        v.w = (cb + 3 < 67) ? sm[(cb + 3) * 65 + row] : 0.f;
        *(float4*)&g_xpt[((size_t)(b * N + n0 + row)) * 68 + cb] = v;
    }
}

// ---------------- prep: f32 aT + bf16 a tiles + axyz ----------------
__global__ void __launch_bounds__(256) prep_a(const float* __restrict__ aG)
{
    int i = blockIdx.x * 256 + threadIdx.x;
    if (i < 128 * 132) {
        int d = i / 132, k = i % 132;
        float v;
        if (k < 128)      v = aG[(3 + k) * 128 + d];
        else if (k < 131) v = aG[(k - 128) * 128 + d];
        else              v = 0.f;
        g_aT[i] = v;
    }
    if (i < 128 * 136) {
        int d = i / 136, k = i % 136;
        float v = (k < 128) ? aG[(3 + k) * 128 + d] : 0.f;
        u16 h, l; bfsplit(v, h, l);
        g_aTh[i] = h; g_aTl[i] = l;
    }
    if (i < 512) {
        int d = i >> 2, c = i & 3;
        g_axyz[i] = (c < 3) ? aG[c * 128 + d] : 0.f;
    }
}

// ---------------- prep_fps: exact f32 MLP + Fp ----------
template<int K4, bool RELU>
__device__ __forceinline__ void gemm128(
    const float* __restrict__ sIn, int inS, const float* __restrict__ sW, int wS,
    const float* __restrict__ bias, float* __restrict__ sOut, int outS, int dOff, int t)
{
    int d_blk = t & 7;
    int r0 = (t >> 3) << 2;
    ull acc[4][8];
#pragma unroll
    for (int i = 0; i < 4; i++)
#pragma unroll
        for (int j = 0; j < 8; j++) acc[i][j] = 0ull;
#pragma unroll 4
    for (int k4 = 0; k4 < K4; k4++) {
        ulonglong2 xv[4];
#pragma unroll
        for (int i = 0; i < 4; i++)
            xv[i] = *(const ulonglong2*)&sIn[(r0 + i) * inS + (k4 << 2)];
#pragma unroll
        for (int j = 0; j < 8; j++) {
            ulonglong2 wv = *(const ulonglong2*)&sW[(dOff + d_blk + (j << 3)) * wS + (k4 << 2)];
#pragma unroll
            for (int i = 0; i < 4; i++) { ffma2(acc[i][j], xv[i].x, wv.x); ffma2(acc[i][j], xv[i].y, wv.y); }
        }
    }
#pragma unroll
    for (int j = 0; j < 8; j++) {
        int d = dOff + d_blk + (j << 3);
        float bb = RELU ? bias[d] : 0.f;
#pragma unroll
        for (int i = 0; i < 4; i++) {
            float v = hsum2(acc[i][j]) + bb;
            if (RELU) v = v > 0.f ? v : 0.f;
            sOut[(r0 + i) * outS + d] = v;
        }
    }
}

__global__ void __launch_bounds__(256) prep_fps(
    const int* __restrict__ fpsIdx,
    const float* __restrict__ w1, const float* __restrict__ b1,
    const float* __restrict__ g1, const float* __restrict__ bt1,
    const float* __restrict__ m1, const float* __restrict__ v1,
    const float* __restrict__ w2, const float* __restrict__ b2,
    const float* __restrict__ g2, const float* __restrict__ bt2,
    const float* __restrict__ m2, const float* __restrict__ v2,
    const float* __restrict__ w3, const float* __restrict__ b3,
    const float* __restrict__ g3, const float* __restrict__ bt3,
    const float* __restrict__ m3, const float* __restrict__ v3,
    float* __restrict__ out)
{
    extern __shared__ float sm[];
    float* W1p = sm;
    float* W2p = sm + 4352;
    float* W3p = sm + 8704;
    float* c1  = sm + 17408;
    float* c2  = sm + 17472;
    float* c3  = sm + 17536;
    float* Xf  = sm + 17664;
    float* Hf  = sm + 26368;
    float* H3f = sm + 35072;
    float* aTs = Xf;

    int t = threadIdx.x;
    int b = blockIdx.x >> 3, pb = (blockIdx.x & 7) << 7;

    for (int idx = t; idx < 64 * 68; idx += 256) {
        int d = idx / 68, k = idx % 68;
        float s1 = g1[d] * rsqrtf(v1[d] + EPSBN);
        float s2 = g2[d] * rsqrtf(v2[d] + EPSBN);
        W1p[idx] = (k < 64) ? w1[d * 67 + 3 + k] * s1
                 : (k < 67) ? w1[d * 67 + (k - 64)] * s1 : 0.f;
        W2p[idx] = (k < 64) ? w2[d * 64 + k] * s2 : 0.f;
    }
    for (int idx = t; idx < 128 * 68; idx += 256) {
        int d = idx / 68, k = idx % 68;
        float s3 = g3[d] * rsqrtf(v3[d] + EPSBN);
        W3p[idx] = (k < 64) ? w3[d * 64 + k] * s3 : 0.f;
    }
    if (t < 64) {
        float s1 = g1[t] * rsqrtf(v1[t] + EPSBN);
        float s2 = g2[t] * rsqrtf(v2[t] + EPSBN);
        c1[t] = (b1[t] - m1[t]) * s1 + bt1[t];
        c2[t] = (b2[t] - m2[t]) * s2 + bt2[t];
    }
    if (t < 128) {
        float s3 = g3[t] * rsqrtf(v3[t] + EPSBN);
        c3[t] = (b3[t] - m3[t]) * s3 + bt3[t];
    }
    __syncthreads();

    for (int idx = t; idx < 128 * 17; idx += 256) {
        int row = idx / 17, c4 = idx % 17;
        int gi = fpsIdx[b * P + pb + row];
        *(float4*)&Xf[row * 68 + (c4 << 2)] =
            *(const float4*)&g_xpt[((size_t)(b * N + gi)) * 68 + (c4 << 2)];
    }
    __syncthreads();
    if (t < 128) {
        out[(b * 3 + 0) * P + pb + t] = Xf[t * 68 + 64];
        out[(b * 3 + 1) * P + pb + t] = Xf[t * 68 + 65];
        out[(b * 3 + 2) * P + pb + t] = Xf[t * 68 + 66];
    }

    gemm128<17, true>(Xf, 68, W1p, 68, c1, Hf, 68, 0, t);
    __syncthreads();
    gemm128<16, true>(Hf, 68, W2p, 68, c2, Xf, 68, 0, t);
    __syncthreads();
    gemm128<16, true>(Xf, 68, W3p, 68, c3, H3f, 132, 0, t);
    gemm128<16, true>(Xf, 68, W3p, 68, c3, H3f, 132, 64, t);
    __syncthreads();
    for (int idx = t; idx < (128 * 132) / 4; idx += 256)
        *(float4*)&aTs[idx << 2] = *(const float4*)&g_aT[idx << 2];
    __syncthreads();
    float* fpOut = g_Fp + (size_t)(b * P + pb) * 128;
    gemm128<32, false>(H3f, 132, aTs, 132, nullptr, fpOut, 128, 0, t);
    gemm128<32, false>(H3f, 132, aTs, 132, nullptr, fpOut, 128, 64, t);
}

// ---------------- HMMA MLP layer (16 warps: m4 x n4, warp m32 x n16) -------
template<bool XYZ, int OUTSTRIDE>
__device__ __forceinline__ void mlp_hmma(
    u32 aH, u32 aL, u32 bH, u32 bL,
    const float* __restrict__ bias, const float* __restrict__ w1x4,
    const float* __restrict__ relx4,
    char* __restrict__ outH, char* __restrict__ outL, int dOff, int t)
{
    int wid = t >> 5, lane = t & 31;
    int mBase = (wid >> 2) << 5;
    int nBase = (wid & 3) << 4;
    float acc[2][2][4];
#pragma unroll
    for (int mt = 0; mt < 2; mt++)
#pragma unroll
        for (int nt = 0; nt < 2; nt++)
#pragma unroll
            for (int q = 0; q < 4; q++) acc[mt][nt][q] = 0.f;

    u32 aoff = (u32)((mBase + (lane & 15)) * 144 + ((lane >> 4) << 4));
    u32 boff = (u32)((nBase + (lane & 7)) * 144 + (((lane >> 3) & 1) << 4));
#pragma unroll
    for (int kk = 0; kk < 4; kk++) {
        u32 kb = (u32)(kk << 5);
        u32 fah0[4], fah1[4], fal0[4], fal1[4];
        ldm_x4(fah0, aH + aoff + kb);
        ldm_x4(fah1, aH + aoff + 16 * 144 + kb);
        ldm_x4(fal0, aL + aoff + kb);
        ldm_x4(fal1, aL + aoff + 16 * 144 + kb);
        u32 fbh[2][2], fbl[2][2];
#pragma unroll
        for (int nt = 0; nt < 2; nt++) {
            ldm_x2(fbh[nt], bH + boff + nt * 8 * 144 + kb);
            ldm_x2(fbl[nt], bL + boff + nt * 8 * 144 + kb);
        }
#pragma unroll
        for (int nt = 0; nt < 2; nt++) {
            mma_bf16(acc[0][nt], fah0, fbh[nt]);
            mma_bf16(acc[1][nt], fah1, fbh[nt]);
            mma_bf16(acc[0][nt], fah0, fbl[nt]);
            mma_bf16(acc[1][nt], fah1, fbl[nt]);
            mma_bf16(acc[0][nt], fal0, fbh[nt]);
            mma_bf16(acc[1][nt], fal1, fbh[nt]);
        }
    }
    int rb = mBase + (lane >> 2);
#pragma unroll
    for (int mt = 0; mt < 2; mt++) {
        int rA = rb + mt * 16, rB = rA + 8;
        float4 rxA, rxB;
        if (XYZ) { rxA = *(const float4*)&relx4[rA * 4]; rxB = *(const float4*)&relx4[rB * 4]; }
#pragma unroll
        for (int nt = 0; nt < 2; nt++) {
            int c = nBase + nt * 8 + ((lane & 3) << 1);
            float b0 = bias[dOff + c], b1 = bias[dOff + c + 1];
            float v00 = acc[mt][nt][0] + b0, v01 = acc[mt][nt][1] + b1;
            float v10 = acc[mt][nt][2] + b0, v11 = acc[mt][nt][3] + b1;
            if (XYZ) {
                float4 w0 = *(const float4*)&w1x4[c * 4];
                float4 w1v = *(const float4*)&w1x4[(c + 1) * 4];
                v00 += rxA.x * w0.x + rxA.y * w0.y + rxA.z * w0.z;
                v01 += rxA.x * w1v.x + rxA.y * w1v.y + rxA.z * w1v.z;
                v10 += rxB.x * w0.x + rxB.y * w0.y + rxB.z * w0.z;
                v11 += rxB.x * w1v.x + rxB.y * w1v.y + rxB.z * w1v.z;
            }
            v00 = fmaxf(v00, 0.f); v01 = fmaxf(v01, 0.f);
            v10 = fmaxf(v10, 0.f); v11 = fmaxf(v11, 0.f);
            u16 h00, l00, h01, l01, h10, l10, h11, l11;
            bfsplit(v00, h00, l00); bfsplit(v01, h01, l01);
            bfsplit(v10, h10, l10); bfsplit(v11, h11, l11);
            int cb2 = (dOff + c) * 2;
            *(u32*)(outH + rA * OUTSTRIDE + cb2) = (u32)h00 | ((u32)h01 << 16);
            *(u32*)(outH + rB * OUTSTRIDE + cb2) = (u32)h10 | ((u32)h11 << 16);
            *(u32*)(outL + rA * OUTSTRIDE + cb2) = (u32)l00 | ((u32)l01 << 16);
            *(u32*)(outL + rB * OUTSTRIDE + cb2) = (u32)l10 | ((u32)l11 << 16);
        }
    }
}

// ---------------- E-half HMMA (16 warps: m4 x n4, warp m32 x n16) ----------
__device__ __forceinline__ void e_hmma(u32 aH, u32 aL, u32 bH, u32 bL,
                                       float* __restrict__ E, int t)
{
    int wid = t >> 5, lane = t & 31;
    int mBase = (wid >> 2) << 5;
    int nBase = (wid & 3) << 4;
    float acc[2][2][4];
#pragma unroll
    for (int mt = 0; mt < 2; mt++)
#pragma unroll
        for (int nt = 0; nt < 2; nt++)
#pragma unroll
            for (int q = 0; q < 4; q++) acc[mt][nt][q] = 0.f;

    u32 aoff = (u32)((mBase + (lane & 15)) * 272 + ((lane >> 4) << 4));
    u32 boff = (u32)((nBase + (lane & 7)) * 272 + (((lane >> 3) & 1) << 4));
#pragma unroll
    for (int kk = 0; kk < 8; kk++) {
        u32 kb = (u32)(kk << 5);
        u32 fah0[4], fah1[4], fal0[4], fal1[4];
        ldm_x4(fah0, aH + aoff + kb);
        ldm_x4(fah1, aH + aoff + 16 * 272 + kb);
        ldm_x4(fal0, aL + aoff + kb);
        ldm_x4(fal1, aL + aoff + 16 * 272 + kb);
        u32 fbh[2][2], fbl[2][2];
#pragma unroll
        for (int nt = 0; nt < 2; nt++) {
            ldm_x2(fbh[nt], bH + boff + nt * 8 * 272 + kb);
            ldm_x2(fbl[nt], bL + boff + nt * 8 * 272 + kb);
        }
#pragma unroll
        for (int nt = 0; nt < 2; nt++) {
            mma_bf16(acc[0][nt], fah0, fbh[nt]);
            mma_bf16(acc[1][nt], fah1, fbh[nt]);
            mma_bf16(acc[0][nt], fah0, fbl[nt]);
            mma_bf16(acc[1][nt], fah1, fbl[nt]);
            mma_bf16(acc[0][nt], fal0, fbh[nt]);
            mma_bf16(acc[1][nt], fal1, fbh[nt]);
        }
    }
    int r0 = mBase + (lane >> 2), cb = (lane & 3) << 1;
#pragma unroll
    for (int mt = 0; mt < 2; mt++)
#pragma unroll
        for (int nt = 0; nt < 2; nt++) {
            int r = r0 + mt * 16, c = nBase + nt * 8 + cb;
            *(float2*)&E[r * 66 + c] = make_float2(acc[mt][nt][0], acc[mt][nt][1]);
            *(float2*)&E[(r + 8) * 66 + c] = make_float2(acc[mt][nt][2], acc[mt][nt][3]);
        }
}

// ---------------- main persistent kernel ----------------
static constexpr int OW1H = 0,      OW1L = 9216,  OW2H = 18432, OW2L = 27648;
static constexpr int OW3H = 36864,  OW3L = 55296;
static constexpr int OBUFA = 73728, OBUFB = 110592;
static constexpr int OH3H = 147456, OH3L = 182272;
static constexpr int ORELX = 217088;
static constexpr int OFPS  = 219136;
static constexpr int OW1X  = 221184;
static constexpr int OC1 = 222208, OC2 = 222464, OC3 = 222720;
static constexpr int ONX = 223232, OROW = 223296;
static constexpr int SMTOTAL = 223840;

__global__ void __launch_bounds__(THREADS, 1) main_kernel(
    const int* __restrict__ fpsIdx, const int* __restrict__ grpIdx,
    const float* __restrict__ w1,
    const float* __restrict__ g1, const float* __restrict__ v1,
    const float* __restrict__ b1, const float* __restrict__ bt1, const float* __restrict__ m1,
    const float* __restrict__ w2,
    const float* __restrict__ g2, const float* __restrict__ v2,
    const float* __restrict__ b2, const float* __restrict__ bt2, const float* __restrict__ m2,
    const float* __restrict__ w3,
    const float* __restrict__ g3, const float* __restrict__ v3,
    const float* __restrict__ b3, const float* __restrict__ bt3, const float* __restrict__ m3,
    float* __restrict__ out)
{
    extern __shared__ __align__(16) char smc[];
    float* relx4 = (float*)(smc + ORELX);
    float* FpS   = (float*)(smc + OFPS);
    float* w1x4  = (float*)(smc + OW1X);
    float* c1s   = (float*)(smc + OC1);
    float* c2s   = (float*)(smc + OC2);
    float* c3s   = (float*)(smc + OC3);
    float* nX    = (float*)(smc + ONX);
    int*  rowGi  = (int*)(smc + OROW);

    int t = threadIdx.x;
    u32 sb = smem_u32(smc);

    for (int idx = t; idx < 64 * 64; idx += THREADS) {
        int d = idx >> 6, k = idx & 63;
        float s1 = g1[d] * rsqrtf(v1[d] + EPSBN);
        float s2 = g2[d] * rsqrtf(v2[d] + EPSBN);
        u16 h, l;
        bfsplit(w1[d * 67 + 3 + k] * s1, h, l);
        *(u16*)(smc + OW1H + d * 144 + k * 2) = h;
        *(u16*)(smc + OW1L + d * 144 + k * 2) = l;
        bfsplit(w2[d * 64 + k] * s2, h, l);
        *(u16*)(smc + OW2H + d * 144 + k * 2) = h;
        *(u16*)(smc + OW2L + d * 144 + k * 2) = l;
    }
    for (int idx = t; idx < 128 * 64; idx += THREADS) {
        int d = idx >> 6, k = idx & 63;
        float s3 = g3[d] * rsqrtf(v3[d] + EPSBN);
        u16 h, l;
        bfsplit(w3[d * 64 + k] * s3, h, l);
        *(u16*)(smc + OW3H + d * 144 + k * 2) = h;
        *(u16*)(smc + OW3L + d * 144 + k * 2) = l;
    }
    if (t < 64) {
        float s1 = g1[t] * rsqrtf(v1[t] + EPSBN);
        float s2 = g2[t] * rsqrtf(v2[t] + EPSBN);
        c1s[t] = (b1[t] - m1[t]) * s1 + bt1[t];
        c2s[t] = (b2[t] - m2[t]) * s2 + bt2[t];
        w1x4[t * 4 + 0] = w1[t * 67 + 0] * s1;
        w1x4[t * 4 + 1] = w1[t * 67 + 1] * s1;
        w1x4[t * 4 + 2] = w1[t * 67 + 2] * s1;
        w1x4[t * 4 + 3] = 0.f;
    }
    if (t < 128) {
        float s3 = g3[t] * rsqrtf(v3[t] + EPSBN);
        c3s[t] = (b3[t] - m3[t]) * s3 + bt3[t];
    }

    u32 aAH = sb + OBUFA, aAL = sb + OBUFA + 18432;
    u32 aBH = sb + OBUFB, aBL = sb + OBUFB + 18432;
    u32 h3H = sb + OH3H,  h3L = sb + OH3L;
    u32 atH = sb + OBUFB, atL = sb + OBUFB + 17408;
    char* h3Hc = smc + OH3H;
    char* h3Lc = smc + OH3L;
    float* Ebuf = (float*)(smc + OBUFA);

    for (int tile = blockIdx.x; tile < NTILES; tile += gridDim.x) {
        __syncthreads();
        int b = tile >> 8, p0 = (tile & 255) << 2;

        if (t < 132)
            rowGi[t] = (t < 128) ? grpIdx[((b * P + p0 + (t >> 5)) << 5) + (t & 31)]
                                 : fpsIdx[b * P + p0 + (t - 128)];
        __syncthreads();
        if (t < 12) {
            int p = t / 3, c = t % 3;
            nX[p * 4 + c] = g_xpt[((size_t)(b * N + rowGi[128 + p])) * 68 + 64 + c];
        }
        if (t < 128)
            ((float4*)FpS)[t] = ((const float4*)(g_Fp + (size_t)(b * P + p0) * 128))[t];
        __syncthreads();

        // gather 128 neighbor rows -> bf16 feat tiles + relx
        for (int idx = t; idx < 128 * 17; idx += THREADS) {
            int row = idx / 17, c4 = idx % 17;
            float4 v = *(const float4*)&g_xpt[((size_t)(b * N + rowGi[row])) * 68 + (c4 << 2)];
            if (c4 < 16) {
                u16 h0, l0, h1, l1, h2, l2, h3v, l3v;
                bfsplit(v.x, h0, l0); bfsplit(v.y, h1, l1);
                bfsplit(v.z, h2, l2); bfsplit(v.w, h3v, l3v);
                u32 off = (u32)(row * 144 + (c4 << 3));
                *(u32*)(smc + OBUFA + off)         = (u32)h0 | ((u32)h1 << 16);
                *(u32*)(smc + OBUFA + off + 4)     = (u32)h2 | ((u32)h3v << 16);
                *(u32*)(smc + OBUFA + 18432 + off)     = (u32)l0 | ((u32)l1 << 16);
                *(u32*)(smc + OBUFA + 18432 + off + 4) = (u32)l2 | ((u32)l3v << 16);
            } else {
                int p = row >> 5;
                relx4[row * 4 + 0] = v.x - nX[p * 4 + 0];
                relx4[row * 4 + 1] = v.y - nX[p * 4 + 1];
                relx4[row * 4 + 2] = v.z - nX[p * 4 + 2];
            }
        }
        __syncthreads();

        // L1: bufA -> bufB (xyz term in epilogue)
        mlp_hmma<true, 144>(aAH, aAL, sb + OW1H, sb + OW1L,
                            c1s, w1x4, relx4, smc + OBUFB, smc + OBUFB + 18432, 0, t);
        __syncthreads();
        // L2: bufB -> bufA
        mlp_hmma<false, 144>(aBH, aBL, sb + OW2H, sb + OW2L,
                             c2s, nullptr, nullptr, smc + OBUFA, smc + OBUFA + 18432, 0, t);
        __syncthreads();
        // stage aT half 0 into bufB while L3 runs
        for (int idx = t; idx < 1088; idx += THREADS) {
            ((uint4*)(smc + OBUFB))[idx] = ((const uint4*)g_aTh)[idx];
            ((uint4*)(smc + OBUFB + 17408))[idx] = ((const uint4*)g_aTl)[idx];
        }
        // L3: bufA -> H3 tiles (stride 272), two halves
        mlp_hmma<false, 272>(aAH, aAL, sb + OW3H, sb + OW3L,
                             c3s, nullptr, nullptr, h3Hc, h3Lc, 0, t);
        mlp_hmma<false, 272>(aAH, aAL, sb + OW3H + 64 * 144, sb + OW3L + 64 * 144,
                             c3s, nullptr, nullptr, h3Hc, h3Lc, 64, t);
        __syncthreads();

#pragma unroll
        for (int hh = 0; hh < 2; hh++) {
            e_hmma(h3H, h3L, atH, atL, Ebuf, t);
            __syncthreads();
            if (hh == 0)
                for (int idx = t; idx < 1088; idx += THREADS) {
                    ((uint4*)(smc + OBUFB))[idx] = ((const uint4*)(g_aTh + 8704))[idx];
                    ((uint4*)(smc + OBUFB + 17408))[idx] = ((const uint4*)(g_aTl + 8704))[idx];
                }
            // softmax + pool: lane pair shares one (pl,dl) column, 16 rows each
            {
                int col = t >> 1, rh = t & 1;
                int pl = col >> 6, dl = col & 63, d = (hh << 6) + dl;
                float Fpd = FpS[pl * 128 + d];
                float4 av = *(const float4*)&g_axyz[d * 4];
                float nx0 = nX[pl * 4], nx1 = nX[pl * 4 + 1], nx2 = nX[pl * 4 + 2];
                float ev_arr[16], mx = -1e30f;
                int rbase = (pl << 5) + (rh << 4);
#pragma unroll
                for (int r = 0; r < 16; r++) {
                    int row = rbase + r;
                    float ev = Fpd - Ebuf[row * 66 + dl]
                        + (nx0 - relx4[row * 4 + 0]) * av.x
                        + (nx1 - relx4[row * 4 + 1]) * av.y
                        + (nx2 - relx4[row * 4 + 2]) * av.z;
                    ev = ev > 0.f ? ev : ALPHA * ev;
                    ev_arr[r] = ev;
                    mx = fmaxf(mx, ev);
                }
                mx = fmaxf(mx, __shfl_xor_sync(0xffffffffu, mx, 1));
                float ssum = 0.f, pooled = 0.f;
#pragma unroll
                for (int r = 0; r < 16; r++) {
                    int row = rbase + r;
                    float ee = __expf(ev_arr[r] - mx);
                    float h3v = bf2f(*(const u16*)(h3Hc + row * 272 + d * 2))
                              + bf2f(*(const u16*)(h3Lc + row * 272 + d * 2));
                    ssum += ee;
                    pooled += ee * h3v;
                }
                ssum   += __shfl_xor_sync(0xffffffffu, ssum, 1);
                pooled += __shfl_xor_sync(0xffffffffu, pooled, 1);
                if (rh == 0)
                    out[OUT2_OFF + (b * 128 + d) * P + p0 + pl] = pooled / ssum;
            }
            __syncthreads();
        }
    }
}

// ---------------------------------------------------------------------------
extern "C" void kernel_launch(void* const* d_in, const int* in_sizes, int n_in,
                              void* d_out, int out_size) {
    const float* xyz    = (const float*)d_in[0];
    const float* pts    = (const float*)d_in[1];
    const int*   fpsIdx = (const int*)d_in[2];
    const int*   grpIdx = (const int*)d_in[3];
    const float* w1 = (const float*)d_in[4];
    const float* b1 = (const float*)d_in[5];
    const float* g1 = (const float*)d_in[6];
    const float* bt1 = (const float*)d_in[7];
    const float* m1 = (const float*)d_in[8];
    const float* v1 = (const float*)d_in[9];
    const float* w2 = (const float*)d_in[10];
    const float* b2 = (const float*)d_in[11];
    const float* g2 = (const float*)d_in[12];
    const float* bt2 = (const float*)d_in[13];
    const float* m2 = (const float*)d_in[14];
    const float* v2 = (const float*)d_in[15];
    const float* w3 = (const float*)d_in[16];
    const float* b3 = (const float*)d_in[17];
    const float* g3 = (const float*)d_in[18];
    const float* bt3 = (const float*)d_in[19];
    const float* m3 = (const float*)d_in[20];
    const float* v3 = (const float*)d_in[21];
    const float* aG = (const float*)d_in[22];
    float* out = (float*)d_out;

    transpose_kernel<<<1024, 256>>>(xyz, pts);
    prep_a<<<68, 256>>>(aG);

    const int fpsSm = 51968 * 4;
    cudaFuncSetAttribute(prep_fps, cudaFuncAttributeMaxDynamicSharedMemorySize, fpsSm);
    prep_fps<<<128, 256, fpsSm>>>(fpsIdx,
        w1, b1, g1, bt1, m1, v1,
        w2, b2, g2, bt2, m2, v2,
        w3, b3, g3, bt3, m3, v3, out);

    cudaFuncSetAttribute(main_kernel, cudaFuncAttributeMaxDynamicSharedMemorySize, SMTOTAL);
    int smCount = 148;
    cudaDeviceGetAttribute(&smCount, cudaDevAttrMultiProcessorCount, 0);

    main_kernel<<<smCount, THREADS, SMTOTAL>>>(
        fpsIdx, grpIdx,
        w1, g1, v1, b1, bt1, m1,
        w2, g2, v2, b2, bt2, m2,
        w3, g3, v3, b3, bt3, m3,
        out);
}

// round 17
// speedup vs baseline: 1.5645x; 1.5645x over previous
#include <cuda_runtime.h>
#include <cuda_bf16.h>

#define EPSBN 1e-5f
#define ALPHA 0.2f

typedef unsigned long long ull;
typedef unsigned int u32;
typedef unsigned short u16;

static constexpr int B = 16, N = 4096, P = 1024;
static constexpr int NTILES = (B * P) / 4;
static constexpr int OUT2_OFF = B * 3 * P;
static constexpr int THREADS = 384;

// [b][n][0..63]=feats, [64..66]=xyz, [67]=0
__device__ __align__(16) float g_xpt[(size_t)B * N * 68];
__device__ __align__(16) float g_aT[128 * 132];
__device__ __align__(16) u16 g_aTh[128 * 136];
__device__ __align__(16) u16 g_aTl[128 * 136];
__device__ __align__(16) float g_axyz[512];
__device__ __align__(16) float g_Fp[(size_t)B * P * 128];

// ---------------- helpers ----------------
__device__ __forceinline__ void ffma2(ull& d, ull a, ull b) {
    asm("fma.rn.f32x2 %0, %1, %2, %0;" : "+l"(d) : "l"(a), "l"(b));
}
__device__ __forceinline__ float hsum2(ull v) {
    float lo, hi; asm("mov.b64 {%0, %1}, %2;" : "=f"(lo), "=f"(hi) : "l"(v));
    return lo + hi;
}
__device__ __forceinline__ float bf2f(u16 v) { return __uint_as_float(((u32)v) << 16); }
__device__ __forceinline__ void bfsplit(float x, u16& h, u16& l) {
    __nv_bfloat16 bh = __float2bfloat16(x);
    h = __nv_bfloat16_raw(bh).x;
    l = __nv_bfloat16_raw(__float2bfloat16(x - __bfloat162float(bh))).x;
}
__device__ __forceinline__ u32 smem_u32(const void* p) {
    u32 a; asm("{ .reg .u64 t; cvta.to.shared.u64 t, %1; cvt.u32.u64 %0, t; }"
               : "=r"(a) : "l"(p));
    return a;
}
__device__ __forceinline__ void ldm_x4(u32* f, u32 addr) {
    asm volatile("ldmatrix.sync.aligned.m8n8.x4.shared.b16 {%0,%1,%2,%3}, [%4];"
        : "=r"(f[0]), "=r"(f[1]), "=r"(f[2]), "=r"(f[3]) : "r"(addr));
}
__device__ __forceinline__ void ldm_x2(u32* f, u32 addr) {
    asm volatile("ldmatrix.sync.aligned.m8n8.x2.shared.b16 {%0,%1}, [%2];"
        : "=r"(f[0]), "=r"(f[1]) : "r"(addr));
}
__device__ __forceinline__ void mma_bf16(float* c, const u32* a, const u32* b) {
    asm volatile("mma.sync.aligned.m16n8k16.row.col.f32.bf16.bf16.f32 "
        "{%0,%1,%2,%3},{%4,%5,%6,%7},{%8,%9},{%0,%1,%2,%3};"
        : "+f"(c[0]), "+f"(c[1]), "+f"(c[2]), "+f"(c[3])
        : "r"(a[0]), "r"(a[1]), "r"(a[2]), "r"(a[3]), "r"(b[0]), "r"(b[1]));
}

// ---------------- transpose (feats first) ----------------
__global__ void __launch_bounds__(256) transpose_kernel(
    const float* __restrict__ xyz, const float* __restrict__ pts)
{
    __shared__ float sm[67 * 65];
    int b = blockIdx.x >> 6, n0 = (blockIdx.x & 63) << 6, t = threadIdx.x;
    for (int idx = t; idx < 67 * 64; idx += 256) {
        int c = idx >> 6, i = idx & 63;
        sm[c * 65 + i] = (c < 64) ? pts[(b * 64 + c) * N + n0 + i]
                                  : xyz[(b * 3 + (c - 64)) * N + n0 + i];
    }
    __syncthreads();
    for (int idx = t; idx < 64 * 17; idx += 256) {
        int row = idx / 17, cb = (idx % 17) << 2;
        float4 v;
        v.x = sm[(cb + 0) * 65 + row];
        v.y = sm[(cb + 1) * 65 + row];
        v.z = sm[(cb + 2) * 65 + row];
        v.w = (cb + 3 < 67) ? sm[(cb + 3) * 65 + row] : 0.f;
        *(float4*)&g_xpt[((size_t)(b * N + n0 + row)) * 68 + cb] = v;
    }
}

// ---------------- prep: f32 aT + bf16 a tiles + axyz ----------------
__global__ void __launch_bounds__(256) prep_a(const float* __restrict__ aG)
{
    int i = blockIdx.x * 256 + threadIdx.x;
    if (i < 128 * 132) {
        int d = i / 132, k = i % 132;
        float v;
        if (k < 128)      v = aG[(3 + k) * 128 + d];
        else if (k < 131) v = aG[(k - 128) * 128 + d];
        else              v = 0.f;
        g_aT[i] = v;
    }
    if (i < 128 * 136) {
        int d = i / 136, k = i % 136;
        float v = (k < 128) ? aG[(3 + k) * 128 + d] : 0.f;
        u16 h, l; bfsplit(v, h, l);
        g_aTh[i] = h; g_aTl[i] = l;
    }
    if (i < 512) {
        int d = i >> 2, c = i & 3;
        g_axyz[i] = (c < 3) ? aG[c * 128 + d] : 0.f;
    }
}

// ---------------- prep_fps: exact f32 MLP + Fp ----------
template<int K4, bool RELU>
__device__ __forceinline__ void gemm128(
    const float* __restrict__ sIn, int inS, const float* __restrict__ sW, int wS,
    const float* __restrict__ bias, float* __restrict__ sOut, int outS, int dOff, int t)
{
    int d_blk = t & 7;
    int r0 = (t >> 3) << 2;
    ull acc[4][8];
#pragma unroll
    for (int i = 0; i < 4; i++)
#pragma unroll
        for (int j = 0; j < 8; j++) acc[i][j] = 0ull;
#pragma unroll 4
    for (int k4 = 0; k4 < K4; k4++) {
        ulonglong2 xv[4];
#pragma unroll
        for (int i = 0; i < 4; i++)
            xv[i] = *(const ulonglong2*)&sIn[(r0 + i) * inS + (k4 << 2)];
#pragma unroll
        for (int j = 0; j < 8; j++) {
            ulonglong2 wv = *(const ulonglong2*)&sW[(dOff + d_blk + (j << 3)) * wS + (k4 << 2)];
#pragma unroll
            for (int i = 0; i < 4; i++) { ffma2(acc[i][j], xv[i].x, wv.x); ffma2(acc[i][j], xv[i].y, wv.y); }
        }
    }
#pragma unroll
    for (int j = 0; j < 8; j++) {
        int d = dOff + d_blk + (j << 3);
        float bb = RELU ? bias[d] : 0.f;
#pragma unroll
        for (int i = 0; i < 4; i++) {
            float v = hsum2(acc[i][j]) + bb;
            if (RELU) v = v > 0.f ? v : 0.f;
            sOut[(r0 + i) * outS + d] = v;
        }
    }
}

__global__ void __launch_bounds__(256) prep_fps(
    const int* __restrict__ fpsIdx,
    const float* __restrict__ w1, const float* __restrict__ b1,
    const float* __restrict__ g1, const float* __restrict__ bt1,
    const float* __restrict__ m1, const float* __restrict__ v1,
    const float* __restrict__ w2, const float* __restrict__ b2,
    const float* __restrict__ g2, const float* __restrict__ bt2,
    const float* __restrict__ m2, const float* __restrict__ v2,
    const float* __restrict__ w3, const float* __restrict__ b3,
    const float* __restrict__ g3, const float* __restrict__ bt3,
    const float* __restrict__ m3, const float* __restrict__ v3,
    float* __restrict__ out)
{
    extern __shared__ float sm[];
    float* W1p = sm;
    float* W2p = sm + 4352;
    float* W3p = sm + 8704;
    float* c1  = sm + 17408;
    float* c2  = sm + 17472;
    float* c3  = sm + 17536;
    float* Xf  = sm + 17664;
    float* Hf  = sm + 26368;
    float* H3f = sm + 35072;
    float* aTs = Xf;

    int t = threadIdx.x;
    int b = blockIdx.x >> 3, pb = (blockIdx.x & 7) << 7;

    for (int idx = t; idx < 64 * 68; idx += 256) {
        int d = idx / 68, k = idx % 68;
        float s1 = g1[d] * rsqrtf(v1[d] + EPSBN);
        float s2 = g2[d] * rsqrtf(v2[d] + EPSBN);
        W1p[idx] = (k < 64) ? w1[d * 67 + 3 + k] * s1
                 : (k < 67) ? w1[d * 67 + (k - 64)] * s1 : 0.f;
        W2p[idx] = (k < 64) ? w2[d * 64 + k] * s2 : 0.f;
    }
    for (int idx = t; idx < 128 * 68; idx += 256) {
        int d = idx / 68, k = idx % 68;
        float s3 = g3[d] * rsqrtf(v3[d] + EPSBN);
        W3p[idx] = (k < 64) ? w3[d * 64 + k] * s3 : 0.f;
    }
    if (t < 64) {
        float s1 = g1[t] * rsqrtf(v1[t] + EPSBN);
        float s2 = g2[t] * rsqrtf(v2[t] + EPSBN);
        c1[t] = (b1[t] - m1[t]) * s1 + bt1[t];
        c2[t] = (b2[t] - m2[t]) * s2 + bt2[t];
    }
    if (t < 128) {
        float s3 = g3[t] * rsqrtf(v3[t] + EPSBN);
        c3[t] = (b3[t] - m3[t]) * s3 + bt3[t];
    }
    __syncthreads();

    for (int idx = t; idx < 128 * 17; idx += 256) {
        int row = idx / 17, c4 = idx % 17;
        int gi = fpsIdx[b * P + pb + row];
        *(float4*)&Xf[row * 68 + (c4 << 2)] =
            *(const float4*)&g_xpt[((size_t)(b * N + gi)) * 68 + (c4 << 2)];
    }
    __syncthreads();
    if (t < 128) {
        out[(b * 3 + 0) * P + pb + t] = Xf[t * 68 + 64];
        out[(b * 3 + 1) * P + pb + t] = Xf[t * 68 + 65];
        out[(b * 3 + 2) * P + pb + t] = Xf[t * 68 + 66];
    }

    gemm128<17, true>(Xf, 68, W1p, 68, c1, Hf, 68, 0, t);
    __syncthreads();
    gemm128<16, true>(Hf, 68, W2p, 68, c2, Xf, 68, 0, t);
    __syncthreads();
    gemm128<16, true>(Xf, 68, W3p, 68, c3, H3f, 132, 0, t);
    gemm128<16, true>(Xf, 68, W3p, 68, c3, H3f, 132, 64, t);
    __syncthreads();
    for (int idx = t; idx < (128 * 132) / 4; idx += 256)
        *(float4*)&aTs[idx << 2] = *(const float4*)&g_aT[idx << 2];
    __syncthreads();
    float* fpOut = g_Fp + (size_t)(b * P + pb) * 128;
    gemm128<32, false>(H3f, 132, aTs, 132, nullptr, fpOut, 128, 0, t);
    gemm128<32, false>(H3f, 132, aTs, 132, nullptr, fpOut, 128, 64, t);
}

// ---------------- HMMA MLP layer (warps 0..7: m4 x n2, warp m32 x n32) -----
template<bool XYZ, int OUTSTRIDE>
__device__ __forceinline__ void mlp_hmma(
    u32 aH, u32 aL, u32 bH, u32 bL,
    const float* __restrict__ bias, const float* __restrict__ w1x4,
    const float* __restrict__ relx4,
    char* __restrict__ outH, char* __restrict__ outL, int dOff, int t)
{
    int wid = t >> 5, lane = t & 31;
    int mBase = (wid >> 1) << 5;
    int nBase = (wid & 1) << 5;
    float acc[2][4][4];
#pragma unroll
    for (int mt = 0; mt < 2; mt++)
#pragma unroll
        for (int nt = 0; nt < 4; nt++)
#pragma unroll
            for (int q = 0; q < 4; q++) acc[mt][nt][q] = 0.f;

    u32 aoff = (u32)((mBase + (lane & 15)) * 144 + ((lane >> 4) << 4));
    u32 boff = (u32)((nBase + (lane & 7)) * 144 + (((lane >> 3) & 1) << 4));
#pragma unroll
    for (int kk = 0; kk < 4; kk++) {
        u32 kb = (u32)(kk << 5);
        u32 fah0[4], fah1[4], fal0[4], fal1[4];
        ldm_x4(fah0, aH + aoff + kb);
        ldm_x4(fah1, aH + aoff + 16 * 144 + kb);
        ldm_x4(fal0, aL + aoff + kb);
        ldm_x4(fal1, aL + aoff + 16 * 144 + kb);
        u32 fbh[4][2], fbl[4][2];
#pragma unroll
        for (int nt = 0; nt < 4; nt++) {
            ldm_x2(fbh[nt], bH + boff + nt * 8 * 144 + kb);
            ldm_x2(fbl[nt], bL + boff + nt * 8 * 144 + kb);
        }
#pragma unroll
        for (int nt = 0; nt < 4; nt++) {
            mma_bf16(acc[0][nt], fah0, fbh[nt]);
            mma_bf16(acc[1][nt], fah1, fbh[nt]);
            mma_bf16(acc[0][nt], fah0, fbl[nt]);
            mma_bf16(acc[1][nt], fah1, fbl[nt]);
            mma_bf16(acc[0][nt], fal0, fbh[nt]);
            mma_bf16(acc[1][nt], fal1, fbh[nt]);
        }
    }
    int rb = mBase + (lane >> 2);
#pragma unroll
    for (int mt = 0; mt < 2; mt++) {
        int rA = rb + mt * 16, rB = rA + 8;
        float4 rxA, rxB;
        if (XYZ) { rxA = *(const float4*)&relx4[rA * 4]; rxB = *(const float4*)&relx4[rB * 4]; }
#pragma unroll
        for (int nt = 0; nt < 4; nt++) {
            int c = nBase + nt * 8 + ((lane & 3) << 1);
            float b0 = bias[dOff + c], b1 = bias[dOff + c + 1];
            float v00 = acc[mt][nt][0] + b0, v01 = acc[mt][nt][1] + b1;
            float v10 = acc[mt][nt][2] + b0, v11 = acc[mt][nt][3] + b1;
            if (XYZ) {
                float4 w0 = *(const float4*)&w1x4[c * 4];
                float4 w1v = *(const float4*)&w1x4[(c + 1) * 4];
                v00 += rxA.x * w0.x + rxA.y * w0.y + rxA.z * w0.z;
                v01 += rxA.x * w1v.x + rxA.y * w1v.y + rxA.z * w1v.z;
                v10 += rxB.x * w0.x + rxB.y * w0.y + rxB.z * w0.z;
                v11 += rxB.x * w1v.x + rxB.y * w1v.y + rxB.z * w1v.z;
            }
            v00 = fmaxf(v00, 0.f); v01 = fmaxf(v01, 0.f);
            v10 = fmaxf(v10, 0.f); v11 = fmaxf(v11, 0.f);
            u16 h00, l00, h01, l01, h10, l10, h11, l11;
            bfsplit(v00, h00, l00); bfsplit(v01, h01, l01);
            bfsplit(v10, h10, l10); bfsplit(v11, h11, l11);
            int cb2 = (dOff + c) * 2;
            *(u32*)(outH + rA * OUTSTRIDE + cb2) = (u32)h00 | ((u32)h01 << 16);
            *(u32*)(outH + rB * OUTSTRIDE + cb2) = (u32)h10 | ((u32)h11 << 16);
            *(u32*)(outL + rA * OUTSTRIDE + cb2) = (u32)l00 | ((u32)l01 << 16);
            *(u32*)(outL + rB * OUTSTRIDE + cb2) = (u32)l10 | ((u32)l11 << 16);
        }
    }
}

// ---------------- E-half HMMA (warps 0..7: m4 x n2, warp m32 x n32) --------
__device__ __forceinline__ void e_hmma(u32 aH, u32 aL, u32 bH, u32 bL,
                                       float* __restrict__ E, int t)
{
    int wid = t >> 5, lane = t & 31;
    int mBase = (wid >> 1) << 5;
    int nBase = (wid & 1) << 5;
    float acc[2][4][4];
#pragma unroll
    for (int mt = 0; mt < 2; mt++)
#pragma unroll
        for (int nt = 0; nt < 4; nt++)
#pragma unroll
            for (int q = 0; q < 4; q++) acc[mt][nt][q] = 0.f;

    u32 aoff = (u32)((mBase + (lane & 15)) * 272 + ((lane >> 4) << 4));
    u32 boff = (u32)((nBase + (lane & 7)) * 272 + (((lane >> 3) & 1) << 4));
#pragma unroll
    for (int kk = 0; kk < 8; kk++) {
        u32 kb = (u32)(kk << 5);
        u32 fah0[4], fah1[4], fal0[4], fal1[4];
        ldm_x4(fah0, aH + aoff + kb);
        ldm_x4(fah1, aH + aoff + 16 * 272 + kb);
        ldm_x4(fal0, aL + aoff + kb);
        ldm_x4(fal1, aL + aoff + 16 * 272 + kb);
        u32 fbh[4][2], fbl[4][2];
#pragma unroll
        for (int nt = 0; nt < 4; nt++) {
            ldm_x2(fbh[nt], bH + boff + nt * 8 * 272 + kb);
            ldm_x2(fbl[nt], bL + boff + nt * 8 * 272 + kb);
        }
#pragma unroll
        for (int nt = 0; nt < 4; nt++) {
            mma_bf16(acc[0][nt], fah0, fbh[nt]);
            mma_bf16(acc[1][nt], fah1, fbh[nt]);
            mma_bf16(acc[0][nt], fah0, fbl[nt]);
            mma_bf16(acc[1][nt], fah1, fbl[nt]);
            mma_bf16(acc[0][nt], fal0, fbh[nt]);
            mma_bf16(acc[1][nt], fal1, fbh[nt]);
        }
    }
    int r0 = mBase + (lane >> 2), cb = (lane & 3) << 1;
#pragma unroll
    for (int mt = 0; mt < 2; mt++)
#pragma unroll
        for (int nt = 0; nt < 4; nt++) {
            int r = r0 + mt * 16, c = nBase + nt * 8 + cb;
            *(float2*)&E[r * 66 + c] = make_float2(acc[mt][nt][0], acc[mt][nt][1]);
            *(float2*)&E[(r + 8) * 66 + c] = make_float2(acc[mt][nt][2], acc[mt][nt][3]);
        }
}

// ---------------- main persistent kernel ----------------
static constexpr int OW1H = 0,      OW1L = 9216,  OW2H = 18432, OW2L = 27648;
static constexpr int OW3H = 36864,  OW3L = 55296;
static constexpr int OBUFA = 73728, OBUFB = 110592;
static constexpr int OH3H = 147456, OH3L = 182272;
static constexpr int ORELX = 217088;
static constexpr int OFPS  = 219136;
static constexpr int OW1X  = 221184;
static constexpr int OC1 = 222208, OC2 = 222464, OC3 = 222720;
static constexpr int ONX = 223232, OROW = 223296;
static constexpr int SMTOTAL = 223840;

__global__ void __launch_bounds__(THREADS, 1) main_kernel(
    const int* __restrict__ fpsIdx, const int* __restrict__ grpIdx,
    const float* __restrict__ w1,
    const float* __restrict__ g1, const float* __restrict__ v1,
    const float* __restrict__ b1, const float* __restrict__ bt1, const float* __restrict__ m1,
    const float* __restrict__ w2,
    const float* __restrict__ g2, const float* __restrict__ v2,
    const float* __restrict__ b2, const float* __restrict__ bt2, const float* __restrict__ m2,
    const float* __restrict__ w3,
    const float* __restrict__ g3, const float* __restrict__ v3,
    const float* __restrict__ b3, const float* __restrict__ bt3, const float* __restrict__ m3,
    float* __restrict__ out)
{
    extern __shared__ __align__(16) char smc[];
    float* relx4 = (float*)(smc + ORELX);
    float* FpS   = (float*)(smc + OFPS);
    float* w1x4  = (float*)(smc + OW1X);
    float* c1s   = (float*)(smc + OC1);
    float* c2s   = (float*)(smc + OC2);
    float* c3s   = (float*)(smc + OC3);
    float* nX    = (float*)(smc + ONX);
    int*  rowGi  = (int*)(smc + OROW);

    int t = threadIdx.x;
    int wid = t >> 5;
    u32 sb = smem_u32(smc);

    for (int idx = t; idx < 64 * 64; idx += THREADS) {
        int d = idx >> 6, k = idx & 63;
        float s1 = g1[d] * rsqrtf(v1[d] + EPSBN);
        float s2 = g2[d] * rsqrtf(v2[d] + EPSBN);
        u16 h, l;
        bfsplit(w1[d * 67 + 3 + k] * s1, h, l);
        *(u16*)(smc + OW1H + d * 144 + k * 2) = h;
        *(u16*)(smc + OW1L + d * 144 + k * 2) = l;
        bfsplit(w2[d * 64 + k] * s2, h, l);
        *(u16*)(smc + OW2H + d * 144 + k * 2) = h;
        *(u16*)(smc + OW2L + d * 144 + k * 2) = l;
    }
    for (int idx = t; idx < 128 * 64; idx += THREADS) {
        int d = idx >> 6, k = idx & 63;
        float s3 = g3[d] * rsqrtf(v3[d] + EPSBN);
        u16 h, l;
        bfsplit(w3[d * 64 + k] * s3, h, l);
        *(u16*)(smc + OW3H + d * 144 + k * 2) = h;
        *(u16*)(smc + OW3L + d * 144 + k * 2) = l;
    }
    if (t < 64) {
        float s1 = g1[t] * rsqrtf(v1[t] + EPSBN);
        float s2 = g2[t] * rsqrtf(v2[t] + EPSBN);
        c1s[t] = (b1[t] - m1[t]) * s1 + bt1[t];
        c2s[t] = (b2[t] - m2[t]) * s2 + bt2[t];
        w1x4[t * 4 + 0] = w1[t * 67 + 0] * s1;
        w1x4[t * 4 + 1] = w1[t * 67 + 1] * s1;
        w1x4[t * 4 + 2] = w1[t * 67 + 2] * s1;
        w1x4[t * 4 + 3] = 0.f;
    }
    if (t < 128) {
        float s3 = g3[t] * rsqrtf(v3[t] + EPSBN);
        c3s[t] = (b3[t] - m3[t]) * s3 + bt3[t];
    }

    u32 aAH = sb + OBUFA, aAL = sb + OBUFA + 18432;
    u32 aBH = sb + OBUFB, aBL = sb + OBUFB + 18432;
    u32 h3H = sb + OH3H,  h3L = sb + OH3L;
    u32 atH = sb + OBUFB, atL = sb + OBUFB + 17408;
    char* h3Hc = smc + OH3H;
    char* h3Lc = smc + OH3L;
    float* Ebuf = (float*)(smc + OBUFA);

    for (int tile = blockIdx.x; tile < NTILES; tile += gridDim.x) {
        __syncthreads();
        int b = tile >> 8, p0 = (tile & 255) << 2;

        if (t < 132)
            rowGi[t] = (t < 128) ? grpIdx[((b * P + p0 + (t >> 5)) << 5) + (t & 31)]
                                 : fpsIdx[b * P + p0 + (t - 128)];
        __syncthreads();
        if (t < 12) {
            int p = t / 3, c = t % 3;
            nX[p * 4 + c] = g_xpt[((size_t)(b * N + rowGi[128 + p])) * 68 + 64 + c];
        }
        if (t < 128)
            ((float4*)FpS)[t] = ((const float4*)(g_Fp + (size_t)(b * P + p0) * 128))[t];
        __syncthreads();

        // gather 128 neighbor rows -> bf16 feat tiles + relx
        for (int idx = t; idx < 128 * 17; idx += THREADS) {
            int row = idx / 17, c4 = idx % 17;
            float4 v = *(const float4*)&g_xpt[((size_t)(b * N + rowGi[row])) * 68 + (c4 << 2)];
            if (c4 < 16) {
                u16 h0, l0, h1, l1, h2, l2, h3v, l3v;
                bfsplit(v.x, h0, l0); bfsplit(v.y, h1, l1);
                bfsplit(v.z, h2, l2); bfsplit(v.w, h3v, l3v);
                u32 off = (u32)(row * 144 + (c4 << 3));
                *(u32*)(smc + OBUFA + off)         = (u32)h0 | ((u32)h1 << 16);
                *(u32*)(smc + OBUFA + off + 4)     = (u32)h2 | ((u32)h3v << 16);
                *(u32*)(smc + OBUFA + 18432 + off)     = (u32)l0 | ((u32)l1 << 16);
                *(u32*)(smc + OBUFA + 18432 + off + 4) = (u32)l2 | ((u32)l3v << 16);
            } else {
                int p = row >> 5;
                relx4[row * 4 + 0] = v.x - nX[p * 4 + 0];
                relx4[row * 4 + 1] = v.y - nX[p * 4 + 1];
                relx4[row * 4 + 2] = v.z - nX[p * 4 + 2];
            }
        }
        __syncthreads();

        // L1: bufA -> bufB (xyz term in epilogue); warps 0..7
        if (wid < 8)
            mlp_hmma<true, 144>(aAH, aAL, sb + OW1H, sb + OW1L,
                                c1s, w1x4, relx4, smc + OBUFB, smc + OBUFB + 18432, 0, t);
        __syncthreads();
        // L2: bufB -> bufA; warps 0..7
        if (wid < 8)
            mlp_hmma<false, 144>(aBH, aBL, sb + OW2H, sb + OW2L,
                                 c2s, nullptr, nullptr, smc + OBUFA, smc + OBUFA + 18432, 0, t);
        __syncthreads();
        // L3 (warps 0..7) while warps 8..11 stage aT half 0 into bufB
        if (wid < 8) {
            mlp_hmma<false, 272>(aAH, aAL, sb + OW3H, sb + OW3L,
                                 c3s, nullptr, nullptr, h3Hc, h3Lc, 0, t);
            mlp_hmma<false, 272>(aAH, aAL, sb + OW3H + 64 * 144, sb + OW3L + 64 * 144,
                                 c3s, nullptr, nullptr, h3Hc, h3Lc, 64, t);
        } else {
            for (int idx = t - 256; idx < 1088; idx += 128) {
                ((uint4*)(smc + OBUFB))[idx] = ((const uint4*)g_aTh)[idx];
                ((uint4*)(smc + OBUFB + 17408))[idx] = ((const uint4*)g_aTl)[idx];
            }
        }
        __syncthreads();

#pragma unroll
        for (int hh = 0; hh < 2; hh++) {
            if (wid < 8) e_hmma(h3H, h3L, atH, atL, Ebuf, t);
            __syncthreads();
            if (hh == 0)
                for (int idx = t; idx < 1088; idx += THREADS) {
                    ((uint4*)(smc + OBUFB))[idx] = ((const uint4*)(g_aTh + 8704))[idx];
                    ((uint4*)(smc + OBUFB + 17408))[idx] = ((const uint4*)(g_aTl + 8704))[idx];
                }
            // softmax + pool: 512 (col,row-half) slots over 384 threads
            for (int slot = t; slot < 512; slot += THREADS) {
                int col = slot >> 1, rh = slot & 1;
                int pl = col >> 6, dl = col & 63, d = (hh << 6) + dl;
                float Fpd = FpS[pl * 128 + d];
                float4 av = *(const float4*)&g_axyz[d * 4];
                float nx0 = nX[pl * 4], nx1 = nX[pl * 4 + 1], nx2 = nX[pl * 4 + 2];
                float ev_arr[16], mx = -1e30f;
                int rbase = (pl << 5) + (rh << 4);
#pragma unroll
                for (int r = 0; r < 16; r++) {
                    int row = rbase + r;
                    float ev = Fpd - Ebuf[row * 66 + dl]
                        + (nx0 - relx4[row * 4 + 0]) * av.x
                        + (nx1 - relx4[row * 4 + 1]) * av.y
                        + (nx2 - relx4[row * 4 + 2]) * av.z;
                    ev = ev > 0.f ? ev : ALPHA * ev;
                    ev_arr[r] = ev;
                    mx = fmaxf(mx, ev);
                }
                mx = fmaxf(mx, __shfl_xor_sync(0xffffffffu, mx, 1));
                float ssum = 0.f, pooled = 0.f;
#pragma unroll
                for (int r = 0; r < 16; r++) {
                    int row = rbase + r;
                    float ee = __expf(ev_arr[r] - mx);
                    float h3v = bf2f(*(const u16*)(h3Hc + row * 272 + d * 2))
                              + bf2f(*(const u16*)(h3Lc + row * 272 + d * 2));
                    ssum += ee;
                    pooled += ee * h3v;
                }
                ssum   += __shfl_xor_sync(0xffffffffu, ssum, 1);
                pooled += __shfl_xor_sync(0xffffffffu, pooled, 1);
                if (rh == 0)
                    out[OUT2_OFF + (b * 128 + d) * P + p0 + pl] = pooled / ssum;
            }
            __syncthreads();
        }
    }
}

// ---------------------------------------------------------------------------
extern "C" void kernel_launch(void* const* d_in, const int* in_sizes, int n_in,
                              void* d_out, int out_size) {
    const float* xyz    = (const float*)d_in[0];
    const float* pts    = (const float*)d_in[1];
    const int*   fpsIdx = (const int*)d_in[2];
    const int*   grpIdx = (const int*)d_in[3];
    const float* w1 = (const float*)d_in[4];
    const float* b1 = (const float*)d_in[5];
    const float* g1 = (const float*)d_in[6];
    const float* bt1 = (const float*)d_in[7];
    const float* m1 = (const float*)d_in[8];
    const float* v1 = (const float*)d_in[9];
    const float* w2 = (const float*)d_in[10];
    const float* b2 = (const float*)d_in[11];
    const float* g2 = (const float*)d_in[12];
    const float* bt2 = (const float*)d_in[13];
    const float* m2 = (const float*)d_in[14];
    const float* v2 = (const float*)d_in[15];
    const float* w3 = (const float*)d_in[16];
    const float* b3 = (const float*)d_in[17];
    const float* g3 = (const float*)d_in[18];
    const float* bt3 = (const float*)d_in[19];
    const float* m3 = (const float*)d_in[20];
    const float* v3 = (const float*)d_in[21];
    const float* aG = (const float*)d_in[22];
    float* out = (float*)d_out;

    transpose_kernel<<<1024, 256>>>(xyz, pts);
    prep_a<<<68, 256>>>(aG);

    const int fpsSm = 51968 * 4;
    cudaFuncSetAttribute(prep_fps, cudaFuncAttributeMaxDynamicSharedMemorySize, fpsSm);
    prep_fps<<<128, 256, fpsSm>>>(fpsIdx,
        w1, b1, g1, bt1, m1, v1,
        w2, b2, g2, bt2, m2, v2,
        w3, b3, g3, bt3, m3, v3, out);

    cudaFuncSetAttribute(main_kernel, cudaFuncAttributeMaxDynamicSharedMemorySize, SMTOTAL);
    int smCount = 148;
    cudaDeviceGetAttribute(&smCount, cudaDevAttrMultiProcessorCount, 0);

    main_kernel<<<smCount, THREADS, SMTOTAL>>>(
        fpsIdx, grpIdx,
        w1, g1, v1, b1, bt1, m1,
        w2, g2, v2, b2, bt2, m2,
        w3, g3, v3, b3, bt3, m3,
        out);
}